// round 1
// baseline (speedup 1.0000x reference)
#include <cuda_runtime.h>
#include <math.h>

#define NBATCH 8
#define SEQLEN 4096
#define DMODEL 512
#define SDIM   64
#define NROWS  (NBATCH*SEQLEN)     /* 32768 */
#define HID    1024
#define LN_EPS 1e-5f

#define SCAN_CHUNK 64
#define SCAN_WARM  64

// ---------------- scratch (device globals; no runtime allocation) ----------
__device__ float g_xn[(size_t)NROWS * DMODEL];            // xn, later overwritten with yn
__device__ float g_xB[(size_t)SEQLEN * NBATCH * SDIM];    // [L, B, S]
__device__ float g_hs[(size_t)SEQLEN * NBATCH * SDIM];    // [L, B, S]
__device__ float g_y [(size_t)NROWS * DMODEL];
__device__ float g_H [(size_t)NROWS * HID];

// ---------------- helpers ---------------------------------------------------
__device__ __forceinline__ float warpSum(float v) {
#pragma unroll
    for (int o = 16; o > 0; o >>= 1) v += __shfl_xor_sync(0xffffffffu, v, o);
    return v;
}

// block of 256 threads
__device__ __forceinline__ float blockSum256(float v) {
    __shared__ float red[8];
    v = warpSum(v);
    if ((threadIdx.x & 31) == 0) red[threadIdx.x >> 5] = v;
    __syncthreads();
    float r = red[0] + red[1] + red[2] + red[3] + red[4] + red[5] + red[6] + red[7];
    __syncthreads();
    return r;
}

// ---------------- K1: layernorm(x) -> xn, and xB = xn @ B ------------------
__global__ __launch_bounds__(256) void k1_ln_xb(
    const float* __restrict__ x,
    const float* __restrict__ gamma, const float* __restrict__ beta,
    const float* __restrict__ Bmat)
{
    int row = blockIdx.x;            // row = b*SEQLEN + l
    int t   = threadIdx.x;           // 256 threads, each owns 2 of 512 dims
    const float* xr = x + (size_t)row * DMODEL;

    __shared__ float sx[DMODEL];
    __shared__ float part[256];

    float v0 = xr[t], v1 = xr[t + 256];
    float mu  = blockSum256(v0 + v1) * (1.0f / DMODEL);
    float d0 = v0 - mu, d1 = v1 - mu;
    float var = blockSum256(d0 * d0 + d1 * d1) * (1.0f / DMODEL);
    float inv = rsqrtf(var + LN_EPS);

    float n0 = d0 * inv * gamma[t]       + beta[t];
    float n1 = d1 * inv * gamma[t + 256] + beta[t + 256];
    sx[t] = n0; sx[t + 256] = n1;
    size_t base = (size_t)row * DMODEL;
    g_xn[base + t]       = n0;
    g_xn[base + t + 256] = n1;
    __syncthreads();

    // xB[s] = sum_d xn[d] * B[d, s];   B is [512, 64] row-major
    int s = t & 63, q = t >> 6;          // 4 partial sums per s
    float acc = 0.f;
    const float* Bp = Bmat + (size_t)(q * 128) * SDIM + s;
#pragma unroll 4
    for (int d = 0; d < 128; d++) acc = fmaf(sx[q * 128 + d], Bp[(size_t)d * SDIM], acc);
    part[t] = acc;
    __syncthreads();
    if (t < 64) {
        int b = row >> 12, l = row & (SEQLEN - 1);
        g_xB[(size_t)l * (NBATCH * SDIM) + b * SDIM + t] =
            part[t] + part[t + 64] + part[t + 128] + part[t + 192];
    }
}

// ---------------- K2: chunked diagonal scan ---------------------------------
// A is lower triangular -> eigenvalues = diag = -(1..64), so A_bar <= e^{-dt}.
// 64-step warmup gives truncation error <= e^{-64} — exact to fp32.
__global__ void k2_scan(const float* __restrict__ log_A,
                        const float* __restrict__ log_dt)
{
    int t = threadIdx.x;             // 512 threads = (b, s) lanes
    int s = t & 63;
    float dt = expf(log_dt[0]);
    float a  = expf(-expf(log_A[s]) * dt);

    int start = blockIdx.x * SCAN_CHUNK;
    int l0 = start - SCAN_WARM; if (l0 < 0) l0 = 0;

    float h = 0.f;
    for (int l = l0; l < start; l++)
        h = fmaf(a, h, g_xB[(size_t)l * 512 + t]);
    for (int l = start; l < start + SCAN_CHUNK; l++) {
        h = fmaf(a, h, g_xB[(size_t)l * 512 + t]);
        g_hs[(size_t)l * 512 + t] = h;
    }
}

// ---------------- K3: y = hs@C + xn*D + x ; yn = LN(y) ----------------------
__global__ __launch_bounds__(256) void k3_y_ln(
    const float* __restrict__ x,
    const float* __restrict__ Cmat, const float* __restrict__ Dvec,
    const float* __restrict__ gamma, const float* __restrict__ beta)
{
    int row = blockIdx.x, t = threadIdx.x;
    int b = row >> 12, l = row & (SEQLEN - 1);

    __shared__ float sh[SDIM];
    if (t < 64) sh[t] = g_hs[(size_t)l * 512 + b * 64 + t];
    __syncthreads();

    float a0 = 0.f, a1 = 0.f;
#pragma unroll
    for (int s = 0; s < 64; s++) {
        float hv = sh[s];
        a0 = fmaf(hv, Cmat[(size_t)s * DMODEL + t],       a0);
        a1 = fmaf(hv, Cmat[(size_t)s * DMODEL + t + 256], a1);
    }
    size_t base = (size_t)row * DMODEL;
    float xn0 = g_xn[base + t], xn1 = g_xn[base + t + 256];
    float y0 = a0 + xn0 * Dvec[t]       + x[base + t];
    float y1 = a1 + xn1 * Dvec[t + 256] + x[base + t + 256];
    g_y[base + t] = y0; g_y[base + t + 256] = y1;

    float mu  = blockSum256(y0 + y1) * (1.0f / DMODEL);
    float d0 = y0 - mu, d1 = y1 - mu;
    float var = blockSum256(d0 * d0 + d1 * d1) * (1.0f / DMODEL);
    float inv = rsqrtf(var + LN_EPS);
    // overwrite g_xn with yn (xn no longer needed)
    g_xn[base + t]       = d0 * inv * gamma[t]       + beta[t];
    g_xn[base + t + 256] = d1 * inv * gamma[t + 256] + beta[t + 256];
}

// ---------------- SGEMM 128x128x8, 256 threads, 8x8 per thread --------------
// EPI == 0 : out = gelu(acc + bias)            (exact gelu via normcdf)
// EPI == 1 : out = acc + bias + add[row, col]
template <int EPI>
__global__ __launch_bounds__(256) void sgemm(
    const float* __restrict__ A, const float* __restrict__ Bm,
    const float* __restrict__ bias, const float* __restrict__ add,
    float* __restrict__ Cout, int M, int N, int K)
{
    __shared__ float As[8][128];
    __shared__ float Bs[8][128];

    int tid = threadIdx.x;
    int bm = blockIdx.y, bn = blockIdx.x;

    const float* Ablk = A + (size_t)bm * 128 * K;
    const float* Bblk = Bm + (size_t)bn * 128;

    int arow = tid >> 1,  acol = (tid & 1) * 4;     // A: 128 rows x 8 k
    int brow = tid >> 5,  bcol = (tid & 31) * 4;    // B: 8 k x 128 cols
    int tx = tid & 15, ty = tid >> 4;

    float c[8][8];
#pragma unroll
    for (int i = 0; i < 8; i++)
#pragma unroll
        for (int j = 0; j < 8; j++) c[i][j] = 0.f;

    for (int k0 = 0; k0 < K; k0 += 8) {
        float4 av = *(const float4*)(Ablk + (size_t)arow * K + k0 + acol);
        float4 bv = *(const float4*)(Bblk + (size_t)(k0 + brow) * N + bcol);
        As[acol + 0][arow] = av.x;
        As[acol + 1][arow] = av.y;
        As[acol + 2][arow] = av.z;
        As[acol + 3][arow] = av.w;
        *(float4*)(&Bs[brow][bcol]) = bv;
        __syncthreads();

#pragma unroll
        for (int k = 0; k < 8; k++) {
            float a[8], b[8];
            *(float4*)(a)     = *(const float4*)(&As[k][ty * 8]);
            *(float4*)(a + 4) = *(const float4*)(&As[k][ty * 8 + 4]);
            *(float4*)(b)     = *(const float4*)(&Bs[k][tx * 8]);
            *(float4*)(b + 4) = *(const float4*)(&Bs[k][tx * 8 + 4]);
#pragma unroll
            for (int i = 0; i < 8; i++)
#pragma unroll
                for (int j = 0; j < 8; j++)
                    c[i][j] = fmaf(a[i], b[j], c[i][j]);
        }
        __syncthreads();
    }

#pragma unroll
    for (int i = 0; i < 8; i++) {
        size_t gm = (size_t)bm * 128 + ty * 8 + i;
#pragma unroll
        for (int j = 0; j < 8; j++) {
            int gn = bn * 128 + tx * 8 + j;
            float v = c[i][j] + bias[gn];
            if (EPI == 0) {
                v = v * normcdff(v);                 // exact gelu
            } else {
                v += add[gm * (size_t)N + gn];
            }
            Cout[gm * (size_t)N + gn] = v;
        }
    }
}

// ---------------- launch -----------------------------------------------------
extern "C" void kernel_launch(void* const* d_in, const int* in_sizes, int n_in,
                              void* d_out, int out_size)
{
    const float* x      = (const float*)d_in[0];
    const float* log_A  = (const float*)d_in[1];
    const float* Bmat   = (const float*)d_in[2];
    const float* Cmat   = (const float*)d_in[3];
    const float* Dvec   = (const float*)d_in[4];
    const float* log_dt = (const float*)d_in[5];
    const float* gamma  = (const float*)d_in[6];
    const float* beta   = (const float*)d_in[7];
    const float* W1     = (const float*)d_in[8];
    const float* b1     = (const float*)d_in[9];
    const float* W2     = (const float*)d_in[10];
    const float* b2     = (const float*)d_in[11];
    float* out = (float*)d_out;

    float *p_xn, *p_y, *p_H;
    cudaGetSymbolAddress((void**)&p_xn, g_xn);
    cudaGetSymbolAddress((void**)&p_y,  g_y);
    cudaGetSymbolAddress((void**)&p_H,  g_H);

    k1_ln_xb<<<NROWS, 256>>>(x, gamma, beta, Bmat);
    k2_scan<<<SEQLEN / SCAN_CHUNK, 512>>>(log_A, log_dt);
    k3_y_ln<<<NROWS, 256>>>(x, Cmat, Dvec, gamma, beta);

    // H = gelu(yn @ W1 + b1)
    sgemm<0><<<dim3(HID / 128, NROWS / 128), 256>>>(p_xn, W1, b1, nullptr, p_H,
                                                    NROWS, HID, DMODEL);
    // out = y + H @ W2 + b2
    sgemm<1><<<dim3(DMODEL / 128, NROWS / 128), 256>>>(p_H, W2, b2, p_y, out,
                                                       NROWS, DMODEL, HID);
}

// round 2
// speedup vs baseline: 1.0003x; 1.0003x over previous
#include <cuda_runtime.h>
#include <math.h>

#define NBATCH 8
#define SEQLEN 4096
#define DMODEL 512
#define SDIM   64
#define NROWS  (NBATCH*SEQLEN)     /* 32768 */
#define HID    1024
#define LN_EPS 1e-5f

#define SCAN_CHUNK 64
#define SCAN_WARM  64

// ---------------- scratch (device globals; no runtime allocation) ----------
__device__ float g_xn[(size_t)NROWS * DMODEL];            // xn, later overwritten with yn
__device__ float g_xB[(size_t)SEQLEN * NBATCH * SDIM];    // [L, B, S]
__device__ float g_hs[(size_t)SEQLEN * NBATCH * SDIM];    // [L, B, S]
__device__ float g_y [(size_t)NROWS * DMODEL];
__device__ float g_H [(size_t)NROWS * HID];

// ---------------- helpers ---------------------------------------------------
__device__ __forceinline__ float warpSum(float v) {
#pragma unroll
    for (int o = 16; o > 0; o >>= 1) v += __shfl_xor_sync(0xffffffffu, v, o);
    return v;
}

// block of 256 threads
__device__ __forceinline__ float blockSum256(float v) {
    __shared__ float red[8];
    v = warpSum(v);
    if ((threadIdx.x & 31) == 0) red[threadIdx.x >> 5] = v;
    __syncthreads();
    float r = red[0] + red[1] + red[2] + red[3] + red[4] + red[5] + red[6] + red[7];
    __syncthreads();
    return r;
}

// ---------------- K1: layernorm(x) -> xn, and xB = xn @ B ------------------
__global__ __launch_bounds__(256) void k1_ln_xb(
    const float* __restrict__ x,
    const float* __restrict__ gamma, const float* __restrict__ beta,
    const float* __restrict__ Bmat)
{
    int row = blockIdx.x;            // row = b*SEQLEN + l
    int t   = threadIdx.x;           // 256 threads, each owns 2 of 512 dims
    const float* xr = x + (size_t)row * DMODEL;

    __shared__ float sx[DMODEL];
    __shared__ float part[256];

    float v0 = xr[t], v1 = xr[t + 256];
    float mu  = blockSum256(v0 + v1) * (1.0f / DMODEL);
    float d0 = v0 - mu, d1 = v1 - mu;
    float var = blockSum256(d0 * d0 + d1 * d1) * (1.0f / DMODEL);
    float inv = rsqrtf(var + LN_EPS);

    float n0 = d0 * inv * gamma[t]       + beta[t];
    float n1 = d1 * inv * gamma[t + 256] + beta[t + 256];
    sx[t] = n0; sx[t + 256] = n1;
    size_t base = (size_t)row * DMODEL;
    g_xn[base + t]       = n0;
    g_xn[base + t + 256] = n1;
    __syncthreads();

    // xB[s] = sum_d xn[d] * B[d, s];   B is [512, 64] row-major
    int s = t & 63, q = t >> 6;          // 4 partial sums per s
    float acc = 0.f;
    const float* Bp = Bmat + (size_t)(q * 128) * SDIM + s;
#pragma unroll 4
    for (int d = 0; d < 128; d++) acc = fmaf(sx[q * 128 + d], Bp[(size_t)d * SDIM], acc);
    part[t] = acc;
    __syncthreads();
    if (t < 64) {
        int b = row >> 12, l = row & (SEQLEN - 1);
        g_xB[(size_t)l * (NBATCH * SDIM) + b * SDIM + t] =
            part[t] + part[t + 64] + part[t + 128] + part[t + 192];
    }
}

// ---------------- K2: chunked diagonal scan ---------------------------------
// A is lower triangular -> eigenvalues = diag = -(1..64), so A_bar <= e^{-dt}.
// 64-step warmup gives truncation error <= e^{-64} — exact to fp32.
__global__ void k2_scan(const float* __restrict__ log_A,
                        const float* __restrict__ log_dt)
{
    int t = threadIdx.x;             // 512 threads = (b, s) lanes
    int s = t & 63;
    float dt = expf(log_dt[0]);
    float a  = expf(-expf(log_A[s]) * dt);

    int start = blockIdx.x * SCAN_CHUNK;
    int l0 = start - SCAN_WARM; if (l0 < 0) l0 = 0;

    float h = 0.f;
    for (int l = l0; l < start; l++)
        h = fmaf(a, h, g_xB[(size_t)l * 512 + t]);
    for (int l = start; l < start + SCAN_CHUNK; l++) {
        h = fmaf(a, h, g_xB[(size_t)l * 512 + t]);
        g_hs[(size_t)l * 512 + t] = h;
    }
}

// ---------------- K3: y = hs@C + xn*D + x ; yn = LN(y) ----------------------
__global__ __launch_bounds__(256) void k3_y_ln(
    const float* __restrict__ x,
    const float* __restrict__ Cmat, const float* __restrict__ Dvec,
    const float* __restrict__ gamma, const float* __restrict__ beta)
{
    int row = blockIdx.x, t = threadIdx.x;
    int b = row >> 12, l = row & (SEQLEN - 1);

    __shared__ float sh[SDIM];
    if (t < 64) sh[t] = g_hs[(size_t)l * 512 + b * 64 + t];
    __syncthreads();

    float a0 = 0.f, a1 = 0.f;
#pragma unroll
    for (int s = 0; s < 64; s++) {
        float hv = sh[s];
        a0 = fmaf(hv, Cmat[(size_t)s * DMODEL + t],       a0);
        a1 = fmaf(hv, Cmat[(size_t)s * DMODEL + t + 256], a1);
    }
    size_t base = (size_t)row * DMODEL;
    float xn0 = g_xn[base + t], xn1 = g_xn[base + t + 256];
    float y0 = a0 + xn0 * Dvec[t]       + x[base + t];
    float y1 = a1 + xn1 * Dvec[t + 256] + x[base + t + 256];
    g_y[base + t] = y0; g_y[base + t + 256] = y1;

    float mu  = blockSum256(y0 + y1) * (1.0f / DMODEL);
    float d0 = y0 - mu, d1 = y1 - mu;
    float var = blockSum256(d0 * d0 + d1 * d1) * (1.0f / DMODEL);
    float inv = rsqrtf(var + LN_EPS);
    // overwrite g_xn with yn (xn no longer needed)
    g_xn[base + t]       = d0 * inv * gamma[t]       + beta[t];
    g_xn[base + t + 256] = d1 * inv * gamma[t + 256] + beta[t + 256];
}

// ---------------- SGEMM 128x128x8, 256 threads, 8x8 per thread --------------
// EPI == 0 : out = gelu(acc + bias)            (exact gelu via normcdf)
// EPI == 1 : out = acc + bias + add[row, col]
template <int EPI>
__global__ __launch_bounds__(256) void sgemm(
    const float* __restrict__ A, const float* __restrict__ Bm,
    const float* __restrict__ bias, const float* __restrict__ add,
    float* __restrict__ Cout, int M, int N, int K)
{
    __shared__ float As[8][128];
    __shared__ float Bs[8][128];

    int tid = threadIdx.x;
    int bm = blockIdx.y, bn = blockIdx.x;

    const float* Ablk = A + (size_t)bm * 128 * K;
    const float* Bblk = Bm + (size_t)bn * 128;

    int arow = tid >> 1,  acol = (tid & 1) * 4;     // A: 128 rows x 8 k
    int brow = tid >> 5,  bcol = (tid & 31) * 4;    // B: 8 k x 128 cols
    int tx = tid & 15, ty = tid >> 4;

    float c[8][8];
#pragma unroll
    for (int i = 0; i < 8; i++)
#pragma unroll
        for (int j = 0; j < 8; j++) c[i][j] = 0.f;

    for (int k0 = 0; k0 < K; k0 += 8) {
        float4 av = *(const float4*)(Ablk + (size_t)arow * K + k0 + acol);
        float4 bv = *(const float4*)(Bblk + (size_t)(k0 + brow) * N + bcol);
        As[acol + 0][arow] = av.x;
        As[acol + 1][arow] = av.y;
        As[acol + 2][arow] = av.z;
        As[acol + 3][arow] = av.w;
        *(float4*)(&Bs[brow][bcol]) = bv;
        __syncthreads();

#pragma unroll
        for (int k = 0; k < 8; k++) {
            float a[8], b[8];
            *(float4*)(a)     = *(const float4*)(&As[k][ty * 8]);
            *(float4*)(a + 4) = *(const float4*)(&As[k][ty * 8 + 4]);
            *(float4*)(b)     = *(const float4*)(&Bs[k][tx * 8]);
            *(float4*)(b + 4) = *(const float4*)(&Bs[k][tx * 8 + 4]);
#pragma unroll
            for (int i = 0; i < 8; i++)
#pragma unroll
                for (int j = 0; j < 8; j++)
                    c[i][j] = fmaf(a[i], b[j], c[i][j]);
        }
        __syncthreads();
    }

#pragma unroll
    for (int i = 0; i < 8; i++) {
        size_t gm = (size_t)bm * 128 + ty * 8 + i;
#pragma unroll
        for (int j = 0; j < 8; j++) {
            int gn = bn * 128 + tx * 8 + j;
            float v = c[i][j] + bias[gn];
            if (EPI == 0) {
                v = v * normcdff(v);                 // exact gelu
            } else {
                v += add[gm * (size_t)N + gn];
            }
            Cout[gm * (size_t)N + gn] = v;
        }
    }
}

// ---------------- launch -----------------------------------------------------
extern "C" void kernel_launch(void* const* d_in, const int* in_sizes, int n_in,
                              void* d_out, int out_size)
{
    const float* x      = (const float*)d_in[0];
    const float* log_A  = (const float*)d_in[1];
    const float* Bmat   = (const float*)d_in[2];
    const float* Cmat   = (const float*)d_in[3];
    const float* Dvec   = (const float*)d_in[4];
    const float* log_dt = (const float*)d_in[5];
    const float* gamma  = (const float*)d_in[6];
    const float* beta   = (const float*)d_in[7];
    const float* W1     = (const float*)d_in[8];
    const float* b1     = (const float*)d_in[9];
    const float* W2     = (const float*)d_in[10];
    const float* b2     = (const float*)d_in[11];
    float* out = (float*)d_out;

    float *p_xn, *p_y, *p_H;
    cudaGetSymbolAddress((void**)&p_xn, g_xn);
    cudaGetSymbolAddress((void**)&p_y,  g_y);
    cudaGetSymbolAddress((void**)&p_H,  g_H);

    k1_ln_xb<<<NROWS, 256>>>(x, gamma, beta, Bmat);
    k2_scan<<<SEQLEN / SCAN_CHUNK, 512>>>(log_A, log_dt);
    k3_y_ln<<<NROWS, 256>>>(x, Cmat, Dvec, gamma, beta);

    // H = gelu(yn @ W1 + b1)
    sgemm<0><<<dim3(HID / 128, NROWS / 128), 256>>>(p_xn, W1, b1, nullptr, p_H,
                                                    NROWS, HID, DMODEL);
    // out = y + H @ W2 + b2
    sgemm<1><<<dim3(DMODEL / 128, NROWS / 128), 256>>>(p_H, W2, b2, p_y, out,
                                                       NROWS, DMODEL, HID);
}

// round 4
// speedup vs baseline: 1.7424x; 1.7419x over previous
#include <cuda_runtime.h>
#include <cuda_bf16.h>
#include <math.h>
#include <stdint.h>

#define NBATCH 8
#define SEQLEN 4096
#define DMODEL 512
#define SDIM   64
#define NROWS  (NBATCH*SEQLEN)     /* 32768 */
#define HID    1024
#define LN_EPS 1e-5f

#define SCAN_CHUNK 64
#define SCAN_WARM  64

#define K1EXT (3*DMODEL)   /* 1536 */
#define K2EXT (3*HID)      /* 3072 */

// ---------------- scratch (device globals; no runtime allocation) ----------
__device__ float g_xn[(size_t)NROWS * DMODEL];
__device__ float g_xB[(size_t)SEQLEN * NBATCH * SDIM];
__device__ float g_hs[(size_t)SEQLEN * NBATCH * SDIM];
__device__ float g_y [(size_t)NROWS * DMODEL];

// extended-K bf16 operands: A' = [hi | lo | hi], B' = [Whi | Whi | Wlo]
__device__ __nv_bfloat16 g_A1ext[(size_t)NROWS * K1EXT];
__device__ __nv_bfloat16 g_Hext [(size_t)NROWS * K2EXT];
__device__ __nv_bfloat16 g_W1ext[(size_t)HID * K1EXT];
__device__ __nv_bfloat16 g_W2ext[(size_t)DMODEL * K2EXT];

// ---------------- generic helpers ------------------------------------------
__device__ __forceinline__ float warpSum(float v) {
#pragma unroll
    for (int o = 16; o > 0; o >>= 1) v += __shfl_xor_sync(0xffffffffu, v, o);
    return v;
}

__device__ __forceinline__ float blockSum256(float v) {
    __shared__ float red[8];
    v = warpSum(v);
    if ((threadIdx.x & 31) == 0) red[threadIdx.x >> 5] = v;
    __syncthreads();
    float r = red[0] + red[1] + red[2] + red[3] + red[4] + red[5] + red[6] + red[7];
    __syncthreads();
    return r;
}

__device__ __forceinline__ uint32_t smem_u32(const void* p) {
    uint32_t a;
    asm("{ .reg .u64 t; cvta.to.shared.u64 t, %1; cvt.u32.u64 %0, t; }" : "=r"(a) : "l"(p));
    return a;
}

#define CPA16(dst, src) \
    asm volatile("cp.async.cg.shared.global [%0], [%1], 16;" :: "r"(dst), "l"(src))
#define CPCOMMIT() asm volatile("cp.async.commit_group;" ::: "memory")
#define CPWAIT2()  asm volatile("cp.async.wait_group 2;" ::: "memory")

// ---------------- K1: layernorm(x) -> xn, and xB = xn @ B ------------------
__global__ __launch_bounds__(256) void k1_ln_xb(
    const float* __restrict__ x,
    const float* __restrict__ gamma, const float* __restrict__ beta,
    const float* __restrict__ Bmat)
{
    int row = blockIdx.x;
    int t   = threadIdx.x;
    const float* xr = x + (size_t)row * DMODEL;

    __shared__ float sx[DMODEL];
    __shared__ float part[256];

    float v0 = xr[t], v1 = xr[t + 256];
    float mu  = blockSum256(v0 + v1) * (1.0f / DMODEL);
    float d0 = v0 - mu, d1 = v1 - mu;
    float var = blockSum256(d0 * d0 + d1 * d1) * (1.0f / DMODEL);
    float inv = rsqrtf(var + LN_EPS);

    float n0 = d0 * inv * gamma[t]       + beta[t];
    float n1 = d1 * inv * gamma[t + 256] + beta[t + 256];
    sx[t] = n0; sx[t + 256] = n1;
    size_t base = (size_t)row * DMODEL;
    g_xn[base + t]       = n0;
    g_xn[base + t + 256] = n1;
    __syncthreads();

    int s = t & 63, q = t >> 6;
    float acc = 0.f;
    const float* Bp = Bmat + (size_t)(q * 128) * SDIM + s;
#pragma unroll 4
    for (int d = 0; d < 128; d++) acc = fmaf(sx[q * 128 + d], Bp[(size_t)d * SDIM], acc);
    part[t] = acc;
    __syncthreads();
    if (t < 64) {
        int b = row >> 12, l = row & (SEQLEN - 1);
        g_xB[(size_t)l * (NBATCH * SDIM) + b * SDIM + t] =
            part[t] + part[t + 64] + part[t + 128] + part[t + 192];
    }
}

// ---------------- K2: chunked diagonal scan ---------------------------------
__global__ void k2_scan(const float* __restrict__ log_A,
                        const float* __restrict__ log_dt)
{
    int t = threadIdx.x;
    int s = t & 63;
    float dt = expf(log_dt[0]);
    float a  = expf(-expf(log_A[s]) * dt);

    int start = blockIdx.x * SCAN_CHUNK;
    int l0 = start - SCAN_WARM; if (l0 < 0) l0 = 0;

    float h = 0.f;
    for (int l = l0; l < start; l++)
        h = fmaf(a, h, g_xB[(size_t)l * 512 + t]);
    for (int l = start; l < start + SCAN_CHUNK; l++) {
        h = fmaf(a, h, g_xB[(size_t)l * 512 + t]);
        g_hs[(size_t)l * 512 + t] = h;
    }
}

// ---------------- K3: y = hs@C + xn*D + x ; yn = LN(y) -> A1ext -------------
__global__ __launch_bounds__(256) void k3_y_ln(
    const float* __restrict__ x,
    const float* __restrict__ Cmat, const float* __restrict__ Dvec,
    const float* __restrict__ gamma, const float* __restrict__ beta)
{
    int row = blockIdx.x, t = threadIdx.x;
    int b = row >> 12, l = row & (SEQLEN - 1);

    __shared__ float sh[SDIM];
    if (t < 64) sh[t] = g_hs[(size_t)l * 512 + b * 64 + t];
    __syncthreads();

    float a0 = 0.f, a1 = 0.f;
#pragma unroll
    for (int s = 0; s < 64; s++) {
        float hv = sh[s];
        a0 = fmaf(hv, Cmat[(size_t)s * DMODEL + t],       a0);
        a1 = fmaf(hv, Cmat[(size_t)s * DMODEL + t + 256], a1);
    }
    size_t base = (size_t)row * DMODEL;
    float xn0 = g_xn[base + t], xn1 = g_xn[base + t + 256];
    float y0 = a0 + xn0 * Dvec[t]       + x[base + t];
    float y1 = a1 + xn1 * Dvec[t + 256] + x[base + t + 256];
    g_y[base + t] = y0; g_y[base + t + 256] = y1;

    float mu  = blockSum256(y0 + y1) * (1.0f / DMODEL);
    float d0 = y0 - mu, d1 = y1 - mu;
    float var = blockSum256(d0 * d0 + d1 * d1) * (1.0f / DMODEL);
    float inv = rsqrtf(var + LN_EPS);
    float n0 = d0 * inv * gamma[t]       + beta[t];
    float n1 = d1 * inv * gamma[t + 256] + beta[t + 256];

    __nv_bfloat16 h0 = __float2bfloat16(n0);
    __nv_bfloat16 h1 = __float2bfloat16(n1);
    __nv_bfloat16 l0v = __float2bfloat16(n0 - __bfloat162float(h0));
    __nv_bfloat16 l1v = __float2bfloat16(n1 - __bfloat162float(h1));

    size_t b3 = (size_t)row * K1EXT;
    // zones: [0:512)=hi, [512:1024)=lo, [1024:1536)=hi
    g_A1ext[b3 + t]              = h0;
    g_A1ext[b3 + t + 256]        = h1;
    g_A1ext[b3 + 512 + t]        = l0v;
    g_A1ext[b3 + 512 + t + 256]  = l1v;
    g_A1ext[b3 + 1024 + t]       = h0;
    g_A1ext[b3 + 1024 + t + 256] = h1;
}

// ---------------- W [K,N] fp32 -> Text [N, 3K] bf16  ([Whi|Whi|Wlo]) -------
__global__ __launch_bounds__(256) void kconv_wt(
    const float* __restrict__ W, int K, int N, __nv_bfloat16* __restrict__ T)
{
    int idx = blockIdx.x * 256 + threadIdx.x;
    if (idx >= K * N) return;
    int k = idx / N, n = idx - k * N;
    float v = W[idx];
    __nv_bfloat16 h = __float2bfloat16(v);
    __nv_bfloat16 lo = __float2bfloat16(v - __bfloat162float(h));
    size_t rb = (size_t)n * (3 * K);
    T[rb + k]         = h;
    T[rb + K + k]     = h;
    T[rb + 2 * K + k] = lo;
}

// ---------------- HMMA GEMM: D = A[M,K'] * B[N,K']^T  (both K-contiguous) ---
// 128x128 tile, BK=64 (128B rows, SW128 swizzle), 3-stage cp.async,
// 8 warps -> 4x2 warp grid of 32x64 warp tiles, mma.m16n8k16 bf16.
// EPI 0: Hext = gelu(D + bias) split -> [hi|lo|hi] zones (width 3N)
// EPI 1: out  = D + bias + addy   (fp32)
#define STAGE_BYTES 32768
#define SMEM_GEMM   (3 * STAGE_BYTES)

__device__ __forceinline__ void load_tile_pair(
    uint32_t sA, uint32_t sB,
    const __nv_bfloat16* __restrict__ Ag, const __nv_bfloat16* __restrict__ Bg,
    int ldk, int tid)
{
#pragma unroll
    for (int i = 0; i < 4; i++) {
        int unit = tid + i * 256;           // 1024 units = 128 rows x 8 x 16B
        int row = unit >> 3, u = unit & 7;
        uint32_t off = row * 128 + u * 16;
        uint32_t phys = off ^ ((off >> 3) & 0x70);
        CPA16(sA + phys, Ag + (size_t)row * ldk + u * 8);
        CPA16(sB + phys, Bg + (size_t)row * ldk + u * 8);
    }
}

template <int EPI, int KEXT>
__global__ __launch_bounds__(256, 1) void gemm_mma(
    const __nv_bfloat16* __restrict__ A, const __nv_bfloat16* __restrict__ Bw,
    const float* __restrict__ bias, const float* __restrict__ addy,
    float* __restrict__ outF, __nv_bfloat16* __restrict__ outE, int N)
{
    extern __shared__ __align__(128) char smem[];
    const int tid = threadIdx.x, lane = tid & 31, wid = tid >> 5;
    const int wm = wid >> 1, wn = wid & 1;
    const int bm = blockIdx.y, bn = blockIdx.x;
    const uint32_t sb = smem_u32(smem);
    constexpr int NC = KEXT / 64;

    const __nv_bfloat16* Ag = A  + (size_t)bm * 128 * KEXT;
    const __nv_bfloat16* Bg = Bw + (size_t)bn * 128 * KEXT;

    float c[2][8][4];
#pragma unroll
    for (int i = 0; i < 2; i++)
#pragma unroll
        for (int j = 0; j < 8; j++)
#pragma unroll
            for (int k = 0; k < 4; k++) c[i][j][k] = 0.f;

    // prologue: stages 0..2 in flight
#pragma unroll
    for (int s = 0; s < 3; s++) {
        load_tile_pair(sb + s * STAGE_BYTES, sb + s * STAGE_BYTES + 16384,
                       Ag + s * 64, Bg + s * 64, KEXT, tid);
        CPCOMMIT();
    }

    const int lrow = lane & 15;
    const int lkb  = (lane >> 4) * 16;

    for (int ch = 0; ch < NC; ch++) {
        CPWAIT2();                 // stage ch complete (always 3 groups pending)
        __syncthreads();
        uint32_t sA = sb + (ch % 3) * STAGE_BYTES;
        uint32_t sB = sA + 16384;

#pragma unroll
        for (int s = 0; s < 4; s++) {      // 4 x k16 per 64-chunk
            uint32_t a[2][4], bfr[8][2];
#pragma unroll
            for (int mt = 0; mt < 2; mt++) {
                uint32_t off = (uint32_t)(wm * 32 + mt * 16 + lrow) * 128 + s * 32 + lkb;
                uint32_t ad = sA + (off ^ ((off >> 3) & 0x70));
                asm volatile("ldmatrix.sync.aligned.m8n8.x4.shared.b16 {%0,%1,%2,%3}, [%4];"
                    : "=r"(a[mt][0]), "=r"(a[mt][1]), "=r"(a[mt][2]), "=r"(a[mt][3])
                    : "r"(ad));
            }
#pragma unroll
            for (int nt = 0; nt < 4; nt++) {
                uint32_t off = (uint32_t)(wn * 64 + nt * 16 + lrow) * 128 + s * 32 + lkb;
                uint32_t ad = sB + (off ^ ((off >> 3) & 0x70));
                uint32_t r0, r1, r2, r3;
                asm volatile("ldmatrix.sync.aligned.m8n8.x4.shared.b16 {%0,%1,%2,%3}, [%4];"
                    : "=r"(r0), "=r"(r1), "=r"(r2), "=r"(r3) : "r"(ad));
                bfr[nt * 2][0] = r0;     bfr[nt * 2][1] = r2;
                bfr[nt * 2 + 1][0] = r1; bfr[nt * 2 + 1][1] = r3;
            }
#pragma unroll
            for (int mt = 0; mt < 2; mt++)
#pragma unroll
                for (int j = 0; j < 8; j++)
                    asm volatile(
                        "mma.sync.aligned.m16n8k16.row.col.f32.bf16.bf16.f32 "
                        "{%0,%1,%2,%3}, {%4,%5,%6,%7}, {%8,%9}, {%0,%1,%2,%3};"
                        : "+f"(c[mt][j][0]), "+f"(c[mt][j][1]),
                          "+f"(c[mt][j][2]), "+f"(c[mt][j][3])
                        : "r"(a[mt][0]), "r"(a[mt][1]), "r"(a[mt][2]), "r"(a[mt][3]),
                          "r"(bfr[j][0]), "r"(bfr[j][1]));
        }
        __syncthreads();
        if (ch + 3 < NC) {
            load_tile_pair(sb + (ch % 3) * STAGE_BYTES,
                           sb + (ch % 3) * STAGE_BYTES + 16384,
                           Ag + (ch + 3) * 64, Bg + (ch + 3) * 64, KEXT, tid);
        }
        CPCOMMIT();                // real or empty group — keeps pending count = 3
    }

    // epilogue
    const int r0l = lane >> 2, cp2 = (lane & 3) * 2;
#pragma unroll
    for (int mt = 0; mt < 2; mt++) {
#pragma unroll
        for (int j = 0; j < 8; j++) {
            int n0 = bn * 128 + wn * 64 + j * 8 + cp2;
            float bb0 = bias[n0], bb1 = bias[n0 + 1];
#pragma unroll
            for (int h = 0; h < 2; h++) {
                int m = bm * 128 + wm * 32 + mt * 16 + r0l + h * 8;
                float v0 = c[mt][j][h * 2 + 0] + bb0;
                float v1 = c[mt][j][h * 2 + 1] + bb1;
                if (EPI == 0) {
                    v0 = v0 * normcdff(v0);     // exact gelu
                    v1 = v1 * normcdff(v1);
                    __nv_bfloat16 h0 = __float2bfloat16(v0);
                    __nv_bfloat16 h1 = __float2bfloat16(v1);
                    __nv_bfloat162 hh; hh.x = h0; hh.y = h1;
                    __nv_bfloat162 ll;
                    ll.x = __float2bfloat16(v0 - __bfloat162float(h0));
                    ll.y = __float2bfloat16(v1 - __bfloat162float(h1));
                    size_t rb = (size_t)m * (3 * N);
                    *(__nv_bfloat162*)(outE + rb + n0)         = hh;
                    *(__nv_bfloat162*)(outE + rb + N + n0)     = ll;
                    *(__nv_bfloat162*)(outE + rb + 2 * N + n0) = hh;
                } else {
                    size_t rb = (size_t)m * N + n0;
                    float2 av = *(const float2*)(addy + rb);
                    float2 ov; ov.x = v0 + av.x; ov.y = v1 + av.y;
                    *(float2*)(outF + rb) = ov;
                }
            }
        }
    }
}

// ---------------- launch -----------------------------------------------------
extern "C" void kernel_launch(void* const* d_in, const int* in_sizes, int n_in,
                              void* d_out, int out_size)
{
    const float* x      = (const float*)d_in[0];
    const float* log_A  = (const float*)d_in[1];
    const float* Bmat   = (const float*)d_in[2];
    const float* Cmat   = (const float*)d_in[3];
    const float* Dvec   = (const float*)d_in[4];
    const float* log_dt = (const float*)d_in[5];
    const float* gamma  = (const float*)d_in[6];
    const float* beta   = (const float*)d_in[7];
    const float* W1     = (const float*)d_in[8];
    const float* b1     = (const float*)d_in[9];
    const float* W2     = (const float*)d_in[10];
    const float* b2     = (const float*)d_in[11];
    float* out = (float*)d_out;

    __nv_bfloat16 *p_A1ext, *p_Hext, *p_W1ext, *p_W2ext;
    float* p_y;
    cudaGetSymbolAddress((void**)&p_A1ext, g_A1ext);
    cudaGetSymbolAddress((void**)&p_Hext,  g_Hext);
    cudaGetSymbolAddress((void**)&p_W1ext, g_W1ext);
    cudaGetSymbolAddress((void**)&p_W2ext, g_W2ext);
    cudaGetSymbolAddress((void**)&p_y,     g_y);

    cudaFuncSetAttribute(gemm_mma<0, K1EXT>,
                         cudaFuncAttributeMaxDynamicSharedMemorySize, SMEM_GEMM);
    cudaFuncSetAttribute(gemm_mma<1, K2EXT>,
                         cudaFuncAttributeMaxDynamicSharedMemorySize, SMEM_GEMM);

    k1_ln_xb<<<NROWS, 256>>>(x, gamma, beta, Bmat);
    k2_scan<<<SEQLEN / SCAN_CHUNK, 512>>>(log_A, log_dt);
    k3_y_ln<<<NROWS, 256>>>(x, Cmat, Dvec, gamma, beta);

    kconv_wt<<<(DMODEL * HID + 255) / 256, 256>>>(W1, DMODEL, HID, p_W1ext);
    kconv_wt<<<(HID * DMODEL + 255) / 256, 256>>>(W2, HID, DMODEL, p_W2ext);

    // H = gelu(yn @ W1 + b1)   M=32768, N=1024, K'=1536
    gemm_mma<0, K1EXT><<<dim3(HID / 128, NROWS / 128), 256, SMEM_GEMM>>>(
        p_A1ext, p_W1ext, b1, nullptr, nullptr, p_Hext, HID);

    // out = H @ W2 + b2 + y    M=32768, N=512, K'=3072
    gemm_mma<1, K2EXT><<<dim3(DMODEL / 128, NROWS / 128), 256, SMEM_GEMM>>>(
        p_Hext, p_W2ext, b2, p_y, out, nullptr, DMODEL);
}

// round 5
// speedup vs baseline: 2.0132x; 1.1554x over previous
#include <cuda_runtime.h>
#include <cuda_bf16.h>
#include <math.h>
#include <stdint.h>

#define NBATCH 8
#define SEQLEN 4096
#define DMODEL 512
#define SDIM   64
#define NROWS  (NBATCH*SEQLEN)     /* 32768 */
#define HID    1024
#define LN_EPS 1e-5f

#define SCAN_CHUNK 64
#define SCAN_WARM  64

#define K1EXT (3*DMODEL)   /* logical K for GEMM1: 1536 */
#define K2EXT (3*HID)      /* logical K for GEMM2: 3072 */

// ---------------- scratch (device globals; no runtime allocation) ----------
__device__ float g_xn[(size_t)NROWS * DMODEL];
__device__ float g_xB[(size_t)SEQLEN * NBATCH * SDIM];
__device__ float g_hs[(size_t)SEQLEN * NBATCH * SDIM];
__device__ float g_y [(size_t)NROWS * DMODEL];

// A-side operands stored [hi | lo] (2K wide); zone 2 (hi again) is remapped in-GEMM.
__device__ __nv_bfloat16 g_A1ext[(size_t)NROWS * (2*DMODEL)];
__device__ __nv_bfloat16 g_Hext [(size_t)NROWS * (2*HID)];
// W operands stored [Whi | Whi | Wlo] (3K wide) — tiny.
__device__ __nv_bfloat16 g_W1ext[(size_t)HID * K1EXT];
__device__ __nv_bfloat16 g_W2ext[(size_t)DMODEL * K2EXT];

// ---------------- generic helpers ------------------------------------------
__device__ __forceinline__ float warpSum(float v) {
#pragma unroll
    for (int o = 16; o > 0; o >>= 1) v += __shfl_xor_sync(0xffffffffu, v, o);
    return v;
}

__device__ __forceinline__ uint32_t smem_u32(const void* p) {
    uint32_t a;
    asm("{ .reg .u64 t; cvta.to.shared.u64 t, %1; cvt.u32.u64 %0, t; }" : "=r"(a) : "l"(p));
    return a;
}

#define CPA16(dst, src) \
    asm volatile("cp.async.cg.shared.global [%0], [%1], 16;" :: "r"(dst), "l"(src))
#define CPCOMMIT() asm volatile("cp.async.commit_group;" ::: "memory")
#define CPWAIT2()  asm volatile("cp.async.wait_group 2;" ::: "memory")

// ================== K1: LN(x) -> xn ; xB = xn @ B  (32-row tiles) ===========
// smem: s_xn[32][516] fp32 | s_B[512][64] fp32 | s_part[2048]
#define K1_SMEM (66048 + 131072 + 8192)

__global__ __launch_bounds__(256) void k1_fused(
    const float* __restrict__ x,
    const float* __restrict__ gamma, const float* __restrict__ beta,
    const float* __restrict__ Bmat)
{
    extern __shared__ __align__(16) char sm1[];
    float* s_xn   = (float*)sm1;                       // [32][516]
    float* s_B    = (float*)(sm1 + 66048);             // [512][64]
    float* s_part = (float*)(sm1 + 66048 + 131072);    // [32][64]

    const int tid = threadIdx.x;
    const int row0 = blockIdx.x * 32;

    // cooperative load B (8192 float4)
    {
        const float4* Bv = (const float4*)Bmat;
        float4* sBv = (float4*)s_B;
#pragma unroll
        for (int i = 0; i < 32; i++) sBv[tid + i * 256] = Bv[tid + i * 256];
    }

    // LN: warp per row, 4 rows per warp
    const int w = tid >> 5, lane = tid & 31;
#pragma unroll
    for (int rr = 0; rr < 4; rr++) {
        int r = w * 4 + rr;
        const float* xr = x + (size_t)(row0 + r) * DMODEL;
        float4 v[4];
        float sum = 0.f, sq = 0.f;
#pragma unroll
        for (int j = 0; j < 4; j++) {
            v[j] = *(const float4*)(xr + j * 128 + lane * 4);
            sum += v[j].x + v[j].y + v[j].z + v[j].w;
            sq  += v[j].x * v[j].x + v[j].y * v[j].y + v[j].z * v[j].z + v[j].w * v[j].w;
        }
        sum = warpSum(sum); sq = warpSum(sq);
        float mu = sum * (1.0f / DMODEL);
        float var = sq * (1.0f / DMODEL) - mu * mu;
        float inv = rsqrtf(var + LN_EPS);
        float* xnr = g_xn + (size_t)(row0 + r) * DMODEL;
#pragma unroll
        for (int j = 0; j < 4; j++) {
            int d = j * 128 + lane * 4;
            float4 g = *(const float4*)(gamma + d);
            float4 b = *(const float4*)(beta + d);
            float4 n;
            n.x = (v[j].x - mu) * inv * g.x + b.x;
            n.y = (v[j].y - mu) * inv * g.y + b.y;
            n.z = (v[j].z - mu) * inv * g.z + b.z;
            n.w = (v[j].w - mu) * inv * g.w + b.w;
            *(float4*)(s_xn + r * 516 + d) = n;
            *(float4*)(xnr + d) = n;
        }
    }
    __syncthreads();

    // proj: thread = (kg, rg, sg); 2 rows x 8 s, K split in halves of 256
    const int kg = tid >> 7;            // 0..1
    const int rg = (tid >> 3) & 15;     // 0..15 (2 rows each)
    const int sg = tid & 7;             // 0..7  (8 s each)
    float acc[2][8];
#pragma unroll
    for (int i = 0; i < 2; i++)
#pragma unroll
        for (int j = 0; j < 8; j++) acc[i][j] = 0.f;

    const float* xr0 = s_xn + (rg * 2 + 0) * 516;
    const float* xr1 = s_xn + (rg * 2 + 1) * 516;
#pragma unroll 8
    for (int k = kg * 256; k < kg * 256 + 256; k++) {
        float x0 = xr0[k], x1 = xr1[k];
        float4 b0 = *(const float4*)(s_B + k * 64 + sg * 8);
        float4 b1 = *(const float4*)(s_B + k * 64 + sg * 8 + 4);
        acc[0][0] = fmaf(x0, b0.x, acc[0][0]); acc[0][1] = fmaf(x0, b0.y, acc[0][1]);
        acc[0][2] = fmaf(x0, b0.z, acc[0][2]); acc[0][3] = fmaf(x0, b0.w, acc[0][3]);
        acc[0][4] = fmaf(x0, b1.x, acc[0][4]); acc[0][5] = fmaf(x0, b1.y, acc[0][5]);
        acc[0][6] = fmaf(x0, b1.z, acc[0][6]); acc[0][7] = fmaf(x0, b1.w, acc[0][7]);
        acc[1][0] = fmaf(x1, b0.x, acc[1][0]); acc[1][1] = fmaf(x1, b0.y, acc[1][1]);
        acc[1][2] = fmaf(x1, b0.z, acc[1][2]); acc[1][3] = fmaf(x1, b0.w, acc[1][3]);
        acc[1][4] = fmaf(x1, b1.x, acc[1][4]); acc[1][5] = fmaf(x1, b1.y, acc[1][5]);
        acc[1][6] = fmaf(x1, b1.z, acc[1][6]); acc[1][7] = fmaf(x1, b1.w, acc[1][7]);
    }
    __syncthreads();
    if (kg == 1) {
#pragma unroll
        for (int i = 0; i < 2; i++)
#pragma unroll
            for (int j = 0; j < 8; j++)
                s_part[(rg * 2 + i) * 64 + sg * 8 + j] = acc[i][j];
    }
    __syncthreads();
    if (kg == 0) {
#pragma unroll
        for (int i = 0; i < 2; i++) {
            int row = row0 + rg * 2 + i;
            int b = row >> 12, l = row & (SEQLEN - 1);
            float* dst = g_xB + (size_t)l * 512 + b * 64 + sg * 8;
#pragma unroll
            for (int j = 0; j < 8; j++)
                dst[j] = acc[i][j] + s_part[(rg * 2 + i) * 64 + sg * 8 + j];
        }
    }
}

// ================== K2: chunked diagonal scan ================================
__global__ void k2_scan(const float* __restrict__ log_A,
                        const float* __restrict__ log_dt)
{
    int t = threadIdx.x;
    int s = t & 63;
    float dt = expf(log_dt[0]);
    float a  = expf(-expf(log_A[s]) * dt);

    int start = blockIdx.x * SCAN_CHUNK;
    int l0 = start - SCAN_WARM; if (l0 < 0) l0 = 0;

    float h = 0.f;
    for (int l = l0; l < start; l++)
        h = fmaf(a, h, g_xB[(size_t)l * 512 + t]);
    for (int l = start; l < start + SCAN_CHUNK; l++) {
        h = fmaf(a, h, g_xB[(size_t)l * 512 + t]);
        g_hs[(size_t)l * 512 + t] = h;
    }
}

// ========== K3: y = hs@C + xn*D + x ; LN(y) -> A1 [hi|lo]  (32-row tiles) ===
// smem: s_C[64][512] | s_y[32][512] | s_hs[32][68]
#define K3_SMEM (131072 + 65536 + 8704)

__global__ __launch_bounds__(256) void k3_fused(
    const float* __restrict__ x,
    const float* __restrict__ Cmat, const float* __restrict__ Dvec,
    const float* __restrict__ gamma, const float* __restrict__ beta)
{
    extern __shared__ __align__(16) char sm3[];
    float* s_C  = (float*)sm3;                   // [64][512]
    float* s_y  = (float*)(sm3 + 131072);        // [32][512]
    float* s_hs = (float*)(sm3 + 131072 + 65536);// [32][68]

    const int tid = threadIdx.x;
    const int row0 = blockIdx.x * 32;

    {   // load C (8192 float4)
        const float4* Cv = (const float4*)Cmat;
        float4* sCv = (float4*)s_C;
#pragma unroll
        for (int i = 0; i < 32; i++) sCv[tid + i * 256] = Cv[tid + i * 256];
    }
    {   // load hs tile: thread -> 8 floats
        int r = tid >> 3, s0 = (tid & 7) * 8;
        int row = row0 + r;
        int b = row >> 12, l = row & (SEQLEN - 1);
        const float* hp = g_hs + (size_t)l * 512 + b * 64 + s0;
        *(float4*)(s_hs + r * 68 + s0)     = *(const float4*)(hp);
        *(float4*)(s_hs + r * 68 + s0 + 4) = *(const float4*)(hp + 4);
    }
    __syncthreads();

    // yC: thread = (rg, dg); 2 rows x (8 x float4) cols
    const int rg = tid >> 4, dg = tid & 15;
    float4 acc[2][8];
#pragma unroll
    for (int i = 0; i < 2; i++)
#pragma unroll
        for (int j = 0; j < 8; j++) acc[i][j] = make_float4(0.f, 0.f, 0.f, 0.f);

    const float* h0p = s_hs + (rg * 2 + 0) * 68;
    const float* h1p = s_hs + (rg * 2 + 1) * 68;
#pragma unroll 4
    for (int k = 0; k < 64; k++) {
        float h0 = h0p[k], h1 = h1p[k];
#pragma unroll
        for (int j = 0; j < 8; j++) {
            float4 c = *(const float4*)(s_C + k * 512 + j * 64 + dg * 4);
            acc[0][j].x = fmaf(h0, c.x, acc[0][j].x);
            acc[0][j].y = fmaf(h0, c.y, acc[0][j].y);
            acc[0][j].z = fmaf(h0, c.z, acc[0][j].z);
            acc[0][j].w = fmaf(h0, c.w, acc[0][j].w);
            acc[1][j].x = fmaf(h1, c.x, acc[1][j].x);
            acc[1][j].y = fmaf(h1, c.y, acc[1][j].y);
            acc[1][j].z = fmaf(h1, c.z, acc[1][j].z);
            acc[1][j].w = fmaf(h1, c.w, acc[1][j].w);
        }
    }

    // y = yC + x + xn*D ; stage in smem + write gmem
#pragma unroll
    for (int i = 0; i < 2; i++) {
        int r = rg * 2 + i;
        size_t base = (size_t)(row0 + r) * DMODEL;
#pragma unroll
        for (int j = 0; j < 8; j++) {
            int d0 = j * 64 + dg * 4;
            float4 xv  = *(const float4*)(x + base + d0);
            float4 xnv = *(const float4*)(g_xn + base + d0);
            float4 dv  = *(const float4*)(Dvec + d0);
            float4 y;
            y.x = acc[i][j].x + xv.x + xnv.x * dv.x;
            y.y = acc[i][j].y + xv.y + xnv.y * dv.y;
            y.z = acc[i][j].z + xv.z + xnv.z * dv.z;
            y.w = acc[i][j].w + xv.w + xnv.w * dv.w;
            *(float4*)(s_y + r * 512 + d0) = y;
            *(float4*)(g_y + base + d0) = y;
        }
    }
    __syncthreads();

    // LN per row -> A1 [hi|lo] bf16
    const int w = tid >> 5, lane = tid & 31;
#pragma unroll
    for (int rr = 0; rr < 4; rr++) {
        int r = w * 4 + rr;
        const float* yr = s_y + r * 512;
        float4 v[4];
        float sum = 0.f, sq = 0.f;
#pragma unroll
        for (int j = 0; j < 4; j++) {
            v[j] = *(const float4*)(yr + j * 128 + lane * 4);
            sum += v[j].x + v[j].y + v[j].z + v[j].w;
            sq  += v[j].x * v[j].x + v[j].y * v[j].y + v[j].z * v[j].z + v[j].w * v[j].w;
        }
        sum = warpSum(sum); sq = warpSum(sq);
        float mu = sum * (1.0f / DMODEL);
        float var = sq * (1.0f / DMODEL) - mu * mu;
        float inv = rsqrtf(var + LN_EPS);
        size_t rowb = (size_t)(row0 + r) * (2 * DMODEL);
#pragma unroll
        for (int j = 0; j < 4; j++) {
            int d = j * 128 + lane * 4;
            float4 g = *(const float4*)(gamma + d);
            float4 b = *(const float4*)(beta + d);
            float n0 = (v[j].x - mu) * inv * g.x + b.x;
            float n1 = (v[j].y - mu) * inv * g.y + b.y;
            float n2 = (v[j].z - mu) * inv * g.z + b.z;
            float n3 = (v[j].w - mu) * inv * g.w + b.w;
            __nv_bfloat16 h0 = __float2bfloat16(n0), h1 = __float2bfloat16(n1);
            __nv_bfloat16 h2 = __float2bfloat16(n2), h3 = __float2bfloat16(n3);
            __nv_bfloat162 hh0; hh0.x = h0; hh0.y = h1;
            __nv_bfloat162 hh1; hh1.x = h2; hh1.y = h3;
            *(__nv_bfloat162*)(g_A1ext + rowb + d)     = hh0;
            *(__nv_bfloat162*)(g_A1ext + rowb + d + 2) = hh1;
            __nv_bfloat162 ll0, ll1;
            ll0.x = __float2bfloat16(n0 - __bfloat162float(h0));
            ll0.y = __float2bfloat16(n1 - __bfloat162float(h1));
            ll1.x = __float2bfloat16(n2 - __bfloat162float(h2));
            ll1.y = __float2bfloat16(n3 - __bfloat162float(h3));
            *(__nv_bfloat162*)(g_A1ext + rowb + DMODEL + d)     = ll0;
            *(__nv_bfloat162*)(g_A1ext + rowb + DMODEL + d + 2) = ll1;
        }
    }
}

// ---------------- W [K,N] fp32 -> T [N, 3K] bf16 ([Whi|Whi|Wlo]), tiled -----
__global__ __launch_bounds__(256) void kconv_wt(
    const float* __restrict__ W, int K, int N, __nv_bfloat16* __restrict__ T)
{
    __shared__ float tile[32][33];
    int k0 = blockIdx.y * 32, n0 = blockIdx.x * 32;
    int tx = threadIdx.x & 31, ty = threadIdx.x >> 5;  // ty 0..7
#pragma unroll
    for (int i = 0; i < 4; i++) {
        int kk = ty + i * 8;
        tile[kk][tx] = W[(size_t)(k0 + kk) * N + n0 + tx];
    }
    __syncthreads();
#pragma unroll
    for (int i = 0; i < 4; i++) {
        int nl = ty + i * 8;
        float v = tile[tx][nl];
        __nv_bfloat16 h = __float2bfloat16(v);
        __nv_bfloat16 lo = __float2bfloat16(v - __bfloat162float(h));
        size_t rb = (size_t)(n0 + nl) * (3 * K);
        T[rb + k0 + tx]         = h;
        T[rb + K + k0 + tx]     = h;
        T[rb + 2 * K + k0 + tx] = lo;
    }
}

// ================== HMMA GEMM ================================================
// D = A'[M,KLOG] * B'[N,KLOG]^T, A physically [hi|lo] (APK wide), zone2 -> zone0.
// 128x128 tile, BK=64, 4-stage cp.async (3 in flight), frag double-buffering.
// EPI 0: outE = gelu(D+bias) split -> [hi|lo] (width 2N). EPI 1: outF = D+bias+addy.
#define STAGE_BYTES 32768
#define SMEM_GEMM   (4 * STAGE_BYTES)

__device__ __forceinline__ void load_tile_pair(
    uint32_t sA, uint32_t sB,
    const __nv_bfloat16* __restrict__ Ag, const __nv_bfloat16* __restrict__ Bg,
    int ldka, int ldkb, int tid)
{
#pragma unroll
    for (int i = 0; i < 4; i++) {
        int unit = tid + i * 256;           // 1024 units = 128 rows x 8 x 16B
        int row = unit >> 3, u = unit & 7;
        uint32_t off = row * 128 + u * 16;
        uint32_t phys = off ^ ((off >> 3) & 0x70);
        CPA16(sA + phys, Ag + (size_t)row * ldka + u * 8);
        CPA16(sB + phys, Bg + (size_t)row * ldkb + u * 8);
    }
}

__device__ __forceinline__ void ldfrags(
    uint32_t sA, uint32_t sB, int s, int wm, int wn, int lrow, int lkb,
    uint32_t a[2][4], uint32_t bfr[8][2])
{
#pragma unroll
    for (int mt = 0; mt < 2; mt++) {
        uint32_t off = (uint32_t)(wm * 32 + mt * 16 + lrow) * 128 + s * 32 + lkb;
        uint32_t ad = sA + (off ^ ((off >> 3) & 0x70));
        asm volatile("ldmatrix.sync.aligned.m8n8.x4.shared.b16 {%0,%1,%2,%3}, [%4];"
            : "=r"(a[mt][0]), "=r"(a[mt][1]), "=r"(a[mt][2]), "=r"(a[mt][3])
            : "r"(ad));
    }
#pragma unroll
    for (int nt = 0; nt < 4; nt++) {
        uint32_t off = (uint32_t)(wn * 64 + nt * 16 + lrow) * 128 + s * 32 + lkb;
        uint32_t ad = sB + (off ^ ((off >> 3) & 0x70));
        uint32_t r0, r1, r2, r3;
        asm volatile("ldmatrix.sync.aligned.m8n8.x4.shared.b16 {%0,%1,%2,%3}, [%4];"
            : "=r"(r0), "=r"(r1), "=r"(r2), "=r"(r3) : "r"(ad));
        bfr[nt * 2][0] = r0;     bfr[nt * 2][1] = r2;
        bfr[nt * 2 + 1][0] = r1; bfr[nt * 2 + 1][1] = r3;
    }
}

template <int EPI, int KLOG, int APK>
__global__ __launch_bounds__(256, 1) void gemm_mma(
    const __nv_bfloat16* __restrict__ A, const __nv_bfloat16* __restrict__ Bw,
    const float* __restrict__ bias, const float* __restrict__ addy,
    float* __restrict__ outF, __nv_bfloat16* __restrict__ outE, int N)
{
    extern __shared__ __align__(128) char smem[];
    const int tid = threadIdx.x, lane = tid & 31, wid = tid >> 5;
    const int wm = wid >> 1, wn = wid & 1;
    const int bm = blockIdx.y, bn = blockIdx.x;
    const uint32_t sb = smem_u32(smem);
    constexpr int NC = KLOG / 64;
    constexpr int Z2 = APK / 64;       // logical chunk where zone2 starts

    const __nv_bfloat16* Ag = A  + (size_t)bm * 128 * APK;
    const __nv_bfloat16* Bg = Bw + (size_t)bn * 128 * KLOG;

    float c[2][8][4];
#pragma unroll
    for (int i = 0; i < 2; i++)
#pragma unroll
        for (int j = 0; j < 8; j++)
#pragma unroll
            for (int k = 0; k < 4; k++) c[i][j][k] = 0.f;

#pragma unroll
    for (int s = 0; s < 3; s++) {      // s < Z2 always (Z2 >= 16)
        load_tile_pair(sb + s * STAGE_BYTES, sb + s * STAGE_BYTES + 16384,
                       Ag + s * 64, Bg + s * 64, APK, KLOG, tid);
        CPCOMMIT();
    }

    const int lrow = lane & 15;
    const int lkb  = (lane >> 4) * 16;

    for (int ch = 0; ch < NC; ch++) {
        CPWAIT2();
        __syncthreads();
        if (ch + 3 < NC) {
            int cn = ch + 3;
            int ca = (cn < Z2) ? cn : cn - Z2;
            load_tile_pair(sb + (cn & 3) * STAGE_BYTES,
                           sb + (cn & 3) * STAGE_BYTES + 16384,
                           Ag + ca * 64, Bg + cn * 64, APK, KLOG, tid);
        }
        CPCOMMIT();

        uint32_t sA = sb + (ch & 3) * STAGE_BYTES;
        uint32_t sB = sA + 16384;

        uint32_t a[2][2][4], bfr[2][8][2];
        ldfrags(sA, sB, 0, wm, wn, lrow, lkb, a[0], bfr[0]);
#pragma unroll
        for (int s = 0; s < 4; s++) {
            if (s < 3) ldfrags(sA, sB, s + 1, wm, wn, lrow, lkb,
                               a[(s + 1) & 1], bfr[(s + 1) & 1]);
            const int cur = s & 1;
#pragma unroll
            for (int mt = 0; mt < 2; mt++)
#pragma unroll
                for (int j = 0; j < 8; j++)
                    asm volatile(
                        "mma.sync.aligned.m16n8k16.row.col.f32.bf16.bf16.f32 "
                        "{%0,%1,%2,%3}, {%4,%5,%6,%7}, {%8,%9}, {%0,%1,%2,%3};"
                        : "+f"(c[mt][j][0]), "+f"(c[mt][j][1]),
                          "+f"(c[mt][j][2]), "+f"(c[mt][j][3])
                        : "r"(a[cur][mt][0]), "r"(a[cur][mt][1]),
                          "r"(a[cur][mt][2]), "r"(a[cur][mt][3]),
                          "r"(bfr[cur][j][0]), "r"(bfr[cur][j][1]));
        }
    }

    // epilogue
    const int r0l = lane >> 2, cp2 = (lane & 3) * 2;
#pragma unroll
    for (int mt = 0; mt < 2; mt++) {
#pragma unroll
        for (int j = 0; j < 8; j++) {
            int n0 = bn * 128 + wn * 64 + j * 8 + cp2;
            float bb0 = bias[n0], bb1 = bias[n0 + 1];
#pragma unroll
            for (int h = 0; h < 2; h++) {
                int m = bm * 128 + wm * 32 + mt * 16 + r0l + h * 8;
                float v0 = c[mt][j][h * 2 + 0] + bb0;
                float v1 = c[mt][j][h * 2 + 1] + bb1;
                if (EPI == 0) {
                    v0 = v0 * normcdff(v0);
                    v1 = v1 * normcdff(v1);
                    __nv_bfloat16 h0 = __float2bfloat16(v0);
                    __nv_bfloat16 h1 = __float2bfloat16(v1);
                    __nv_bfloat162 hh; hh.x = h0; hh.y = h1;
                    __nv_bfloat162 ll;
                    ll.x = __float2bfloat16(v0 - __bfloat162float(h0));
                    ll.y = __float2bfloat16(v1 - __bfloat162float(h1));
                    size_t rb = (size_t)m * (2 * N);
                    *(__nv_bfloat162*)(outE + rb + n0)     = hh;
                    *(__nv_bfloat162*)(outE + rb + N + n0) = ll;
                } else {
                    size_t rb = (size_t)m * N + n0;
                    float2 av = *(const float2*)(addy + rb);
                    float2 ov; ov.x = v0 + av.x; ov.y = v1 + av.y;
                    *(float2*)(outF + rb) = ov;
                }
            }
        }
    }
}

// ---------------- launch -----------------------------------------------------
extern "C" void kernel_launch(void* const* d_in, const int* in_sizes, int n_in,
                              void* d_out, int out_size)
{
    const float* x      = (const float*)d_in[0];
    const float* log_A  = (const float*)d_in[1];
    const float* Bmat   = (const float*)d_in[2];
    const float* Cmat   = (const float*)d_in[3];
    const float* Dvec   = (const float*)d_in[4];
    const float* log_dt = (const float*)d_in[5];
    const float* gamma  = (const float*)d_in[6];
    const float* beta   = (const float*)d_in[7];
    const float* W1     = (const float*)d_in[8];
    const float* b1     = (const float*)d_in[9];
    const float* W2     = (const float*)d_in[10];
    const float* b2     = (const float*)d_in[11];
    float* out = (float*)d_out;

    __nv_bfloat16 *p_A1ext, *p_Hext, *p_W1ext, *p_W2ext;
    float* p_y;
    cudaGetSymbolAddress((void**)&p_A1ext, g_A1ext);
    cudaGetSymbolAddress((void**)&p_Hext,  g_Hext);
    cudaGetSymbolAddress((void**)&p_W1ext, g_W1ext);
    cudaGetSymbolAddress((void**)&p_W2ext, g_W2ext);
    cudaGetSymbolAddress((void**)&p_y,     g_y);

    cudaFuncSetAttribute(k1_fused, cudaFuncAttributeMaxDynamicSharedMemorySize, K1_SMEM);
    cudaFuncSetAttribute(k3_fused, cudaFuncAttributeMaxDynamicSharedMemorySize, K3_SMEM);
    cudaFuncSetAttribute((const void*)gemm_mma<0, K1EXT, 2*DMODEL>,
                         cudaFuncAttributeMaxDynamicSharedMemorySize, SMEM_GEMM);
    cudaFuncSetAttribute((const void*)gemm_mma<1, K2EXT, 2*HID>,
                         cudaFuncAttributeMaxDynamicSharedMemorySize, SMEM_GEMM);

    kconv_wt<<<dim3(HID / 32, DMODEL / 32), 256>>>(W1, DMODEL, HID, p_W1ext);
    kconv_wt<<<dim3(DMODEL / 32, HID / 32), 256>>>(W2, HID, DMODEL, p_W2ext);

    k1_fused<<<NROWS / 32, 256, K1_SMEM>>>(x, gamma, beta, Bmat);
    k2_scan<<<SEQLEN / SCAN_CHUNK, 512>>>(log_A, log_dt);
    k3_fused<<<NROWS / 32, 256, K3_SMEM>>>(x, Cmat, Dvec, gamma, beta);

    // H = gelu(yn @ W1 + b1)   M=32768, N=1024, K'=1536 (A phys 1024)
    gemm_mma<0, K1EXT, 2*DMODEL><<<dim3(HID / 128, NROWS / 128), 256, SMEM_GEMM>>>(
        p_A1ext, p_W1ext, b1, nullptr, nullptr, p_Hext, HID);

    // out = H @ W2 + b2 + y    M=32768, N=512, K'=3072 (A phys 2048)
    gemm_mma<1, K2EXT, 2*HID><<<dim3(DMODEL / 128, NROWS / 128), 256, SMEM_GEMM>>>(
        p_Hext, p_W2ext, b2, p_y, out, nullptr, DMODEL);
}

// round 6
// speedup vs baseline: 2.2787x; 1.1319x over previous
#include <cuda_runtime.h>
#include <cuda_bf16.h>
#include <math.h>
#include <stdint.h>

#define NBATCH 8
#define SEQLEN 4096
#define DMODEL 512
#define SDIM   64
#define NROWS  (NBATCH*SEQLEN)     /* 32768 */
#define HID    1024
#define LN_EPS 1e-5f

#define SCAN_CHUNK 16
#define SCAN_WARM  24

#define K1EXT (3*DMODEL)   /* logical K for GEMM1: 1536 */
#define K2EXT (3*HID)      /* logical K for GEMM2: 3072 */

// ---------------- scratch (device globals; no runtime allocation) ----------
__device__ float g_xn[(size_t)NROWS * DMODEL];
__device__ float g_xB[(size_t)SEQLEN * NBATCH * SDIM];
__device__ float g_hs[(size_t)SEQLEN * NBATCH * SDIM];
__device__ float g_y [(size_t)NROWS * DMODEL];

// A-side operands stored [hi | lo] (2K wide); zone 2 (hi again) is remapped in-GEMM.
__device__ __nv_bfloat16 g_A1ext[(size_t)NROWS * (2*DMODEL)];
__device__ __nv_bfloat16 g_Hext [(size_t)NROWS * (2*HID)];
// W operands stored [Whi | Whi | Wlo] (3K wide) — tiny.
__device__ __nv_bfloat16 g_W1ext[(size_t)HID * K1EXT];
__device__ __nv_bfloat16 g_W2ext[(size_t)DMODEL * K2EXT];

// ---------------- generic helpers ------------------------------------------
__device__ __forceinline__ float warpSum(float v) {
#pragma unroll
    for (int o = 16; o > 0; o >>= 1) v += __shfl_xor_sync(0xffffffffu, v, o);
    return v;
}

__device__ __forceinline__ uint32_t smem_u32(const void* p) {
    uint32_t a;
    asm("{ .reg .u64 t; cvta.to.shared.u64 t, %1; cvt.u32.u64 %0, t; }" : "=r"(a) : "l"(p));
    return a;
}

#define CPA16(dst, src) \
    asm volatile("cp.async.cg.shared.global [%0], [%1], 16;" :: "r"(dst), "l"(src))
#define CPCOMMIT() asm volatile("cp.async.commit_group;" ::: "memory")
#define CPWAIT1()  asm volatile("cp.async.wait_group 1;" ::: "memory")

// ================== K1: LN(x) -> xn ; xB = xn @ B  (32-row tiles) ===========
// smem: s_xn[32][516] fp32 | s_B[512][64] fp32 | s_part[2048]
#define K1_SMEM (66048 + 131072 + 8192)

__global__ __launch_bounds__(256) void k1_fused(
    const float* __restrict__ x,
    const float* __restrict__ gamma, const float* __restrict__ beta,
    const float* __restrict__ Bmat)
{
    extern __shared__ __align__(16) char sm1[];
    float* s_xn   = (float*)sm1;                       // [32][516]
    float* s_B    = (float*)(sm1 + 66048);             // [512][64]
    float* s_part = (float*)(sm1 + 66048 + 131072);    // [32][64]

    const int tid = threadIdx.x;
    const int row0 = blockIdx.x * 32;

    {
        const float4* Bv = (const float4*)Bmat;
        float4* sBv = (float4*)s_B;
#pragma unroll
        for (int i = 0; i < 32; i++) sBv[tid + i * 256] = Bv[tid + i * 256];
    }

    const int w = tid >> 5, lane = tid & 31;
#pragma unroll
    for (int rr = 0; rr < 4; rr++) {
        int r = w * 4 + rr;
        const float* xr = x + (size_t)(row0 + r) * DMODEL;
        float4 v[4];
        float sum = 0.f, sq = 0.f;
#pragma unroll
        for (int j = 0; j < 4; j++) {
            v[j] = *(const float4*)(xr + j * 128 + lane * 4);
            sum += v[j].x + v[j].y + v[j].z + v[j].w;
            sq  += v[j].x * v[j].x + v[j].y * v[j].y + v[j].z * v[j].z + v[j].w * v[j].w;
        }
        sum = warpSum(sum); sq = warpSum(sq);
        float mu = sum * (1.0f / DMODEL);
        float var = sq * (1.0f / DMODEL) - mu * mu;
        float inv = rsqrtf(var + LN_EPS);
        float* xnr = g_xn + (size_t)(row0 + r) * DMODEL;
#pragma unroll
        for (int j = 0; j < 4; j++) {
            int d = j * 128 + lane * 4;
            float4 g = *(const float4*)(gamma + d);
            float4 b = *(const float4*)(beta + d);
            float4 n;
            n.x = (v[j].x - mu) * inv * g.x + b.x;
            n.y = (v[j].y - mu) * inv * g.y + b.y;
            n.z = (v[j].z - mu) * inv * g.z + b.z;
            n.w = (v[j].w - mu) * inv * g.w + b.w;
            *(float4*)(s_xn + r * 516 + d) = n;
            *(float4*)(xnr + d) = n;
        }
    }
    __syncthreads();

    const int kg = tid >> 7;
    const int rg = (tid >> 3) & 15;
    const int sg = tid & 7;
    float acc[2][8];
#pragma unroll
    for (int i = 0; i < 2; i++)
#pragma unroll
        for (int j = 0; j < 8; j++) acc[i][j] = 0.f;

    const float* xr0 = s_xn + (rg * 2 + 0) * 516;
    const float* xr1 = s_xn + (rg * 2 + 1) * 516;
#pragma unroll 8
    for (int k = kg * 256; k < kg * 256 + 256; k++) {
        float x0 = xr0[k], x1 = xr1[k];
        float4 b0 = *(const float4*)(s_B + k * 64 + sg * 8);
        float4 b1 = *(const float4*)(s_B + k * 64 + sg * 8 + 4);
        acc[0][0] = fmaf(x0, b0.x, acc[0][0]); acc[0][1] = fmaf(x0, b0.y, acc[0][1]);
        acc[0][2] = fmaf(x0, b0.z, acc[0][2]); acc[0][3] = fmaf(x0, b0.w, acc[0][3]);
        acc[0][4] = fmaf(x0, b1.x, acc[0][4]); acc[0][5] = fmaf(x0, b1.y, acc[0][5]);
        acc[0][6] = fmaf(x0, b1.z, acc[0][6]); acc[0][7] = fmaf(x0, b1.w, acc[0][7]);
        acc[1][0] = fmaf(x1, b0.x, acc[1][0]); acc[1][1] = fmaf(x1, b0.y, acc[1][1]);
        acc[1][2] = fmaf(x1, b0.z, acc[1][2]); acc[1][3] = fmaf(x1, b0.w, acc[1][3]);
        acc[1][4] = fmaf(x1, b1.x, acc[1][4]); acc[1][5] = fmaf(x1, b1.y, acc[1][5]);
        acc[1][6] = fmaf(x1, b1.z, acc[1][6]); acc[1][7] = fmaf(x1, b1.w, acc[1][7]);
    }
    __syncthreads();
    if (kg == 1) {
#pragma unroll
        for (int i = 0; i < 2; i++)
#pragma unroll
            for (int j = 0; j < 8; j++)
                s_part[(rg * 2 + i) * 64 + sg * 8 + j] = acc[i][j];
    }
    __syncthreads();
    if (kg == 0) {
#pragma unroll
        for (int i = 0; i < 2; i++) {
            int row = row0 + rg * 2 + i;
            int b = row >> 12, l = row & (SEQLEN - 1);
            float* dst = g_xB + (size_t)l * 512 + b * 64 + sg * 8;
#pragma unroll
            for (int j = 0; j < 8; j++)
                dst[j] = acc[i][j] + s_part[(rg * 2 + i) * 64 + sg * 8 + j];
        }
    }
}

// ================== K2: chunked diagonal scan (short warmup) ================
// a <= e^{-1}; 24-step warmup -> truncation < 4e-11 relative (invisible in fp32).
__global__ void k2_scan(const float* __restrict__ log_A,
                        const float* __restrict__ log_dt)
{
    int t = threadIdx.x;
    int s = t & 63;
    float dt = expf(log_dt[0]);
    float a  = expf(-expf(log_A[s]) * dt);

    int start = blockIdx.x * SCAN_CHUNK;
    int l0 = start - SCAN_WARM; if (l0 < 0) l0 = 0;

    float h = 0.f;
    for (int l = l0; l < start; l++)
        h = fmaf(a, h, g_xB[(size_t)l * 512 + t]);
#pragma unroll
    for (int i = 0; i < SCAN_CHUNK; i++) {
        int l = start + i;
        h = fmaf(a, h, g_xB[(size_t)l * 512 + t]);
        g_hs[(size_t)l * 512 + t] = h;
    }
}

// ========== K3: y = hs@C + xn*D + x ; LN(y) -> A1 [hi|lo]  (32-row tiles) ===
#define K3_SMEM (131072 + 65536 + 8704)

__global__ __launch_bounds__(256) void k3_fused(
    const float* __restrict__ x,
    const float* __restrict__ Cmat, const float* __restrict__ Dvec,
    const float* __restrict__ gamma, const float* __restrict__ beta)
{
    extern __shared__ __align__(16) char sm3[];
    float* s_C  = (float*)sm3;                   // [64][512]
    float* s_y  = (float*)(sm3 + 131072);        // [32][512]
    float* s_hs = (float*)(sm3 + 131072 + 65536);// [32][68]

    const int tid = threadIdx.x;
    const int row0 = blockIdx.x * 32;

    {
        const float4* Cv = (const float4*)Cmat;
        float4* sCv = (float4*)s_C;
#pragma unroll
        for (int i = 0; i < 32; i++) sCv[tid + i * 256] = Cv[tid + i * 256];
    }
    {
        int r = tid >> 3, s0 = (tid & 7) * 8;
        int row = row0 + r;
        int b = row >> 12, l = row & (SEQLEN - 1);
        const float* hp = g_hs + (size_t)l * 512 + b * 64 + s0;
        *(float4*)(s_hs + r * 68 + s0)     = *(const float4*)(hp);
        *(float4*)(s_hs + r * 68 + s0 + 4) = *(const float4*)(hp + 4);
    }
    __syncthreads();

    const int rg = tid >> 4, dg = tid & 15;
    float4 acc[2][8];
#pragma unroll
    for (int i = 0; i < 2; i++)
#pragma unroll
        for (int j = 0; j < 8; j++) acc[i][j] = make_float4(0.f, 0.f, 0.f, 0.f);

    const float* h0p = s_hs + (rg * 2 + 0) * 68;
    const float* h1p = s_hs + (rg * 2 + 1) * 68;
#pragma unroll 4
    for (int k = 0; k < 64; k++) {
        float h0 = h0p[k], h1 = h1p[k];
#pragma unroll
        for (int j = 0; j < 8; j++) {
            float4 c = *(const float4*)(s_C + k * 512 + j * 64 + dg * 4);
            acc[0][j].x = fmaf(h0, c.x, acc[0][j].x);
            acc[0][j].y = fmaf(h0, c.y, acc[0][j].y);
            acc[0][j].z = fmaf(h0, c.z, acc[0][j].z);
            acc[0][j].w = fmaf(h0, c.w, acc[0][j].w);
            acc[1][j].x = fmaf(h1, c.x, acc[1][j].x);
            acc[1][j].y = fmaf(h1, c.y, acc[1][j].y);
            acc[1][j].z = fmaf(h1, c.z, acc[1][j].z);
            acc[1][j].w = fmaf(h1, c.w, acc[1][j].w);
        }
    }

#pragma unroll
    for (int i = 0; i < 2; i++) {
        int r = rg * 2 + i;
        size_t base = (size_t)(row0 + r) * DMODEL;
#pragma unroll
        for (int j = 0; j < 8; j++) {
            int d0 = j * 64 + dg * 4;
            float4 xv  = *(const float4*)(x + base + d0);
            float4 xnv = *(const float4*)(g_xn + base + d0);
            float4 dv  = *(const float4*)(Dvec + d0);
            float4 y;
            y.x = acc[i][j].x + xv.x + xnv.x * dv.x;
            y.y = acc[i][j].y + xv.y + xnv.y * dv.y;
            y.z = acc[i][j].z + xv.z + xnv.z * dv.z;
            y.w = acc[i][j].w + xv.w + xnv.w * dv.w;
            *(float4*)(s_y + r * 512 + d0) = y;
            *(float4*)(g_y + base + d0) = y;
        }
    }
    __syncthreads();

    const int w = tid >> 5, lane = tid & 31;
#pragma unroll
    for (int rr = 0; rr < 4; rr++) {
        int r = w * 4 + rr;
        const float* yr = s_y + r * 512;
        float4 v[4];
        float sum = 0.f, sq = 0.f;
#pragma unroll
        for (int j = 0; j < 4; j++) {
            v[j] = *(const float4*)(yr + j * 128 + lane * 4);
            sum += v[j].x + v[j].y + v[j].z + v[j].w;
            sq  += v[j].x * v[j].x + v[j].y * v[j].y + v[j].z * v[j].z + v[j].w * v[j].w;
        }
        sum = warpSum(sum); sq = warpSum(sq);
        float mu = sum * (1.0f / DMODEL);
        float var = sq * (1.0f / DMODEL) - mu * mu;
        float inv = rsqrtf(var + LN_EPS);
        size_t rowb = (size_t)(row0 + r) * (2 * DMODEL);
#pragma unroll
        for (int j = 0; j < 4; j++) {
            int d = j * 128 + lane * 4;
            float4 g = *(const float4*)(gamma + d);
            float4 b = *(const float4*)(beta + d);
            float n0 = (v[j].x - mu) * inv * g.x + b.x;
            float n1 = (v[j].y - mu) * inv * g.y + b.y;
            float n2 = (v[j].z - mu) * inv * g.z + b.z;
            float n3 = (v[j].w - mu) * inv * g.w + b.w;
            __nv_bfloat16 h0 = __float2bfloat16(n0), h1 = __float2bfloat16(n1);
            __nv_bfloat16 h2 = __float2bfloat16(n2), h3 = __float2bfloat16(n3);
            __nv_bfloat162 hh0; hh0.x = h0; hh0.y = h1;
            __nv_bfloat162 hh1; hh1.x = h2; hh1.y = h3;
            *(__nv_bfloat162*)(g_A1ext + rowb + d)     = hh0;
            *(__nv_bfloat162*)(g_A1ext + rowb + d + 2) = hh1;
            __nv_bfloat162 ll0, ll1;
            ll0.x = __float2bfloat16(n0 - __bfloat162float(h0));
            ll0.y = __float2bfloat16(n1 - __bfloat162float(h1));
            ll1.x = __float2bfloat16(n2 - __bfloat162float(h2));
            ll1.y = __float2bfloat16(n3 - __bfloat162float(h3));
            *(__nv_bfloat162*)(g_A1ext + rowb + DMODEL + d)     = ll0;
            *(__nv_bfloat162*)(g_A1ext + rowb + DMODEL + d + 2) = ll1;
        }
    }
}

// ---------------- W [K,N] fp32 -> T [N, 3K] bf16 ([Whi|Whi|Wlo]), tiled -----
__global__ __launch_bounds__(256) void kconv_wt(
    const float* __restrict__ W, int K, int N, __nv_bfloat16* __restrict__ T)
{
    __shared__ float tile[32][33];
    int k0 = blockIdx.y * 32, n0 = blockIdx.x * 32;
    int tx = threadIdx.x & 31, ty = threadIdx.x >> 5;
#pragma unroll
    for (int i = 0; i < 4; i++) {
        int kk = ty + i * 8;
        tile[kk][tx] = W[(size_t)(k0 + kk) * N + n0 + tx];
    }
    __syncthreads();
#pragma unroll
    for (int i = 0; i < 4; i++) {
        int nl = ty + i * 8;
        float v = tile[tx][nl];
        __nv_bfloat16 h = __float2bfloat16(v);
        __nv_bfloat16 lo = __float2bfloat16(v - __bfloat162float(h));
        size_t rb = (size_t)(n0 + nl) * (3 * K);
        T[rb + k0 + tx]         = h;
        T[rb + K + k0 + tx]     = h;
        T[rb + 2 * K + k0 + tx] = lo;
    }
}

// ================== HMMA GEMM ================================================
// 3-stage cp.async (96 KB) -> 2 CTAs/SM; single-buffered frags (reg <= 128).
#define STAGE_BYTES 32768
#define SMEM_GEMM   (3 * STAGE_BYTES)

__device__ __forceinline__ void load_tile_pair(
    uint32_t sA, uint32_t sB,
    const __nv_bfloat16* __restrict__ Ag, const __nv_bfloat16* __restrict__ Bg,
    int ldka, int ldkb, int tid)
{
#pragma unroll
    for (int i = 0; i < 4; i++) {
        int unit = tid + i * 256;
        int row = unit >> 3, u = unit & 7;
        uint32_t off = row * 128 + u * 16;
        uint32_t phys = off ^ ((off >> 3) & 0x70);
        CPA16(sA + phys, Ag + (size_t)row * ldka + u * 8);
        CPA16(sB + phys, Bg + (size_t)row * ldkb + u * 8);
    }
}

template <int EPI, int KLOG, int APK>
__global__ __launch_bounds__(256, 2) void gemm_mma(
    const __nv_bfloat16* __restrict__ A, const __nv_bfloat16* __restrict__ Bw,
    const float* __restrict__ bias, const float* __restrict__ addy,
    float* __restrict__ outF, __nv_bfloat16* __restrict__ outE, int N)
{
    extern __shared__ __align__(128) char smem[];
    const int tid = threadIdx.x, lane = tid & 31, wid = tid >> 5;
    const int wm = wid >> 1, wn = wid & 1;
    const int bm = blockIdx.y, bn = blockIdx.x;
    const uint32_t sb = smem_u32(smem);
    constexpr int NC = KLOG / 64;
    constexpr int Z2 = APK / 64;

    const __nv_bfloat16* Ag = A  + (size_t)bm * 128 * APK;
    const __nv_bfloat16* Bg = Bw + (size_t)bn * 128 * KLOG;

    float c[2][8][4];
#pragma unroll
    for (int i = 0; i < 2; i++)
#pragma unroll
        for (int j = 0; j < 8; j++)
#pragma unroll
            for (int k = 0; k < 4; k++) c[i][j][k] = 0.f;

#pragma unroll
    for (int s = 0; s < 2; s++) {
        load_tile_pair(sb + s * STAGE_BYTES, sb + s * STAGE_BYTES + 16384,
                       Ag + s * 64, Bg + s * 64, APK, KLOG, tid);
        CPCOMMIT();
    }

    const int lrow = lane & 15;
    const int lkb  = (lane >> 4) * 16;

    for (int ch = 0; ch < NC; ch++) {
        CPWAIT1();
        __syncthreads();
        if (ch + 2 < NC) {
            int cn = ch + 2;
            int ca = (cn < Z2) ? cn : cn - Z2;
            load_tile_pair(sb + (cn % 3) * STAGE_BYTES,
                           sb + (cn % 3) * STAGE_BYTES + 16384,
                           Ag + ca * 64, Bg + cn * 64, APK, KLOG, tid);
        }
        CPCOMMIT();

        uint32_t sA = sb + (ch % 3) * STAGE_BYTES;
        uint32_t sB = sA + 16384;

#pragma unroll
        for (int s = 0; s < 4; s++) {
            uint32_t a[2][4], bfr[8][2];
#pragma unroll
            for (int mt = 0; mt < 2; mt++) {
                uint32_t off = (uint32_t)(wm * 32 + mt * 16 + lrow) * 128 + s * 32 + lkb;
                uint32_t ad = sA + (off ^ ((off >> 3) & 0x70));
                asm volatile("ldmatrix.sync.aligned.m8n8.x4.shared.b16 {%0,%1,%2,%3}, [%4];"
                    : "=r"(a[mt][0]), "=r"(a[mt][1]), "=r"(a[mt][2]), "=r"(a[mt][3])
                    : "r"(ad));
            }
#pragma unroll
            for (int nt = 0; nt < 4; nt++) {
                uint32_t off = (uint32_t)(wn * 64 + nt * 16 + lrow) * 128 + s * 32 + lkb;
                uint32_t ad = sB + (off ^ ((off >> 3) & 0x70));
                uint32_t r0, r1, r2, r3;
                asm volatile("ldmatrix.sync.aligned.m8n8.x4.shared.b16 {%0,%1,%2,%3}, [%4];"
                    : "=r"(r0), "=r"(r1), "=r"(r2), "=r"(r3) : "r"(ad));
                bfr[nt * 2][0] = r0;     bfr[nt * 2][1] = r2;
                bfr[nt * 2 + 1][0] = r1; bfr[nt * 2 + 1][1] = r3;
            }
#pragma unroll
            for (int mt = 0; mt < 2; mt++)
#pragma unroll
                for (int j = 0; j < 8; j++)
                    asm volatile(
                        "mma.sync.aligned.m16n8k16.row.col.f32.bf16.bf16.f32 "
                        "{%0,%1,%2,%3}, {%4,%5,%6,%7}, {%8,%9}, {%0,%1,%2,%3};"
                        : "+f"(c[mt][j][0]), "+f"(c[mt][j][1]),
                          "+f"(c[mt][j][2]), "+f"(c[mt][j][3])
                        : "r"(a[mt][0]), "r"(a[mt][1]), "r"(a[mt][2]), "r"(a[mt][3]),
                          "r"(bfr[j][0]), "r"(bfr[j][1]));
        }
    }

    const int r0l = lane >> 2, cp2 = (lane & 3) * 2;
#pragma unroll
    for (int mt = 0; mt < 2; mt++) {
#pragma unroll
        for (int j = 0; j < 8; j++) {
            int n0 = bn * 128 + wn * 64 + j * 8 + cp2;
            float bb0 = bias[n0], bb1 = bias[n0 + 1];
#pragma unroll
            for (int h = 0; h < 2; h++) {
                int m = bm * 128 + wm * 32 + mt * 16 + r0l + h * 8;
                float v0 = c[mt][j][h * 2 + 0] + bb0;
                float v1 = c[mt][j][h * 2 + 1] + bb1;
                if (EPI == 0) {
                    v0 = v0 * normcdff(v0);
                    v1 = v1 * normcdff(v1);
                    __nv_bfloat16 h0 = __float2bfloat16(v0);
                    __nv_bfloat16 h1 = __float2bfloat16(v1);
                    __nv_bfloat162 hh; hh.x = h0; hh.y = h1;
                    __nv_bfloat162 ll;
                    ll.x = __float2bfloat16(v0 - __bfloat162float(h0));
                    ll.y = __float2bfloat16(v1 - __bfloat162float(h1));
                    size_t rb = (size_t)m * (2 * N);
                    *(__nv_bfloat162*)(outE + rb + n0)     = hh;
                    *(__nv_bfloat162*)(outE + rb + N + n0) = ll;
                } else {
                    size_t rb = (size_t)m * N + n0;
                    float2 av = *(const float2*)(addy + rb);
                    float2 ov; ov.x = v0 + av.x; ov.y = v1 + av.y;
                    *(float2*)(outF + rb) = ov;
                }
            }
        }
    }
}

// ---------------- launch -----------------------------------------------------
extern "C" void kernel_launch(void* const* d_in, const int* in_sizes, int n_in,
                              void* d_out, int out_size)
{
    const float* x      = (const float*)d_in[0];
    const float* log_A  = (const float*)d_in[1];
    const float* Bmat   = (const float*)d_in[2];
    const float* Cmat   = (const float*)d_in[3];
    const float* Dvec   = (const float*)d_in[4];
    const float* log_dt = (const float*)d_in[5];
    const float* gamma  = (const float*)d_in[6];
    const float* beta   = (const float*)d_in[7];
    const float* W1     = (const float*)d_in[8];
    const float* b1     = (const float*)d_in[9];
    const float* W2     = (const float*)d_in[10];
    const float* b2     = (const float*)d_in[11];
    float* out = (float*)d_out;

    __nv_bfloat16 *p_A1ext, *p_Hext, *p_W1ext, *p_W2ext;
    float* p_y;
    cudaGetSymbolAddress((void**)&p_A1ext, g_A1ext);
    cudaGetSymbolAddress((void**)&p_Hext,  g_Hext);
    cudaGetSymbolAddress((void**)&p_W1ext, g_W1ext);
    cudaGetSymbolAddress((void**)&p_W2ext, g_W2ext);
    cudaGetSymbolAddress((void**)&p_y,     g_y);

    cudaFuncSetAttribute(k1_fused, cudaFuncAttributeMaxDynamicSharedMemorySize, K1_SMEM);
    cudaFuncSetAttribute(k3_fused, cudaFuncAttributeMaxDynamicSharedMemorySize, K3_SMEM);
    cudaFuncSetAttribute((const void*)gemm_mma<0, K1EXT, 2*DMODEL>,
                         cudaFuncAttributeMaxDynamicSharedMemorySize, SMEM_GEMM);
    cudaFuncSetAttribute((const void*)gemm_mma<1, K2EXT, 2*HID>,
                         cudaFuncAttributeMaxDynamicSharedMemorySize, SMEM_GEMM);

    kconv_wt<<<dim3(HID / 32, DMODEL / 32), 256>>>(W1, DMODEL, HID, p_W1ext);
    kconv_wt<<<dim3(DMODEL / 32, HID / 32), 256>>>(W2, HID, DMODEL, p_W2ext);

    k1_fused<<<NROWS / 32, 256, K1_SMEM>>>(x, gamma, beta, Bmat);
    k2_scan<<<SEQLEN / SCAN_CHUNK, 512>>>(log_A, log_dt);
    k3_fused<<<NROWS / 32, 256, K3_SMEM>>>(x, Cmat, Dvec, gamma, beta);

    // H = gelu(yn @ W1 + b1)   M=32768, N=1024, K'=1536 (A phys 1024)
    gemm_mma<0, K1EXT, 2*DMODEL><<<dim3(HID / 128, NROWS / 128), 256, SMEM_GEMM>>>(
        p_A1ext, p_W1ext, b1, nullptr, nullptr, p_Hext, HID);

    // out = H @ W2 + b2 + y    M=32768, N=512, K'=3072 (A phys 2048)
    gemm_mma<1, K2EXT, 2*HID><<<dim3(DMODEL / 128, NROWS / 128), 256, SMEM_GEMM>>>(
        p_Hext, p_W2ext, b2, p_y, out, nullptr, DMODEL);
}